// round 11
// baseline (speedup 1.0000x reference)
#include <cuda_runtime.h>

#define NSLICE 24
#define H 256
#define W 256
#define OH 512
#define OW 512

// One block = 8 output rows (one tile) of one (b,s) image: rows 8g..8g+7.
// 128 threads split as 2 row-groups x 64 col-threads:
//   rg = t>>6 handles tile rows 4rg..4rg+3, c = t&63 handles cols 8c..8c+7.
// Each thread: 4 input rows (iy = 4g - 1 + 2rg + j', j'=0..3) loaded as
// front-batched LDG.128 (+ shuffle halos), 4 output rows written as
// st.global.cs.v8.f32 (STG.256, 1KB contiguous per warp per store).
__device__ __forceinline__ void stg256_cs(float* p, const float* o) {
    asm volatile(
        "st.global.cs.v8.f32 [%0], {%1,%2,%3,%4,%5,%6,%7,%8};"
        :: "l"(p), "f"(o[0]), "f"(o[1]), "f"(o[2]), "f"(o[3]),
           "f"(o[4]), "f"(o[5]), "f"(o[6]), "f"(o[7])
        : "memory");
}

__global__ __launch_bounds__(128, 8) void convT_kernel(
    const float* __restrict__ x,
    const float* __restrict__ w,
    const float* __restrict__ bias,
    float* __restrict__ out)
{
    const int t    = threadIdx.x;      // 0..127
    const int lane = t & 31;
    const int rg   = t >> 6;           // 0 or 1: tile rows 4rg..4rg+3
    const int c    = t & 63;           // col-thread: output cols 8c..8c+7
    const int g    = blockIdx.x;       // 0..63 -> output rows 8g..8g+7
    const int bs   = blockIdx.y;       // 0..191
    const int s    = bs % NSLICE;

    const float* xb = x + (unsigned)bs * (H * W);

    // 4 input rows j'=0..3: iy = 4g - 1 + 2rg + j'. Cols: float4 at ix=4c,
    // halos L (ix=4c-1) and R (ix=4c+4) via shuffle (c is consecutive within
    // each warp) with scalar-LDG fallback at warp edges.
    float4 v[4];
    float L[4], R[4];
    #pragma unroll
    for (int j = 0; j < 4; ++j) {
        const int iy = 4 * g - 1 + 2 * rg + j;
        float4 q = make_float4(0.f, 0.f, 0.f, 0.f);
        if (iy >= 0 && iy < H)
            q = *reinterpret_cast<const float4*>(xb + iy * W + 4 * c);
        v[j] = q;
    }

    const unsigned full = 0xFFFFFFFFu;
    #pragma unroll
    for (int j = 0; j < 4; ++j) {
        L[j] = __shfl_up_sync(full, v[j].w, 1);
        R[j] = __shfl_down_sync(full, v[j].x, 1);
    }

    if (lane == 0) {
        #pragma unroll
        for (int j = 0; j < 4; ++j) {
            const int iy = 4 * g - 1 + 2 * rg + j;
            L[j] = (c > 0 && iy >= 0 && iy < H) ? xb[iy * W + 4 * c - 1] : 0.f;
        }
    }
    if (lane == 31) {
        #pragma unroll
        for (int j = 0; j < 4; ++j) {
            const int iy = 4 * g - 1 + 2 * rg + j;
            R[j] = (4 * c + 4 < W && iy >= 0 && iy < H) ? xb[iy * W + 4 * c + 4] : 0.f;
        }
    }

    const float4 wr0 = *reinterpret_cast<const float4*>(w + s * 16 + 0);
    const float4 wr1 = *reinterpret_cast<const float4*>(w + s * 16 + 4);
    const float4 wr2 = *reinterpret_cast<const float4*>(w + s * 16 + 8);
    const float4 wr3 = *reinterpret_cast<const float4*>(w + s * 16 + 12);
    const float b0 = bias[s];

    float* ob = out + ((unsigned)bs * (OH * OW)
                       + (unsigned)(8 * g + 4 * rg) * OW + 8 * c);

    // Local output rows 0..3 (tile rows 4rg+0..3) use local input rows:
    //   row0: j'0 (w3*), j'1 (w1*)   row1: j'1 (w2*), j'2 (w0*)
    //   row2: j'1 (w3*), j'2 (w1*)   row3: j'2 (w2*), j'3 (w0*)
    // Col pattern over [L, v.x, v.y, v.z, v.w, R] (ix = 4c-1 .. 4c+4):
    //   o0 = a3*L   + a1*v.x   o1 = a2*v.x + a0*v.y
    //   o2 = a3*v.x + a1*v.y   o3 = a2*v.y + a0*v.z
    //   o4 = a3*v.y + a1*v.z   o5 = a2*v.z + a0*v.w
    //   o6 = a3*v.z + a1*v.w   o7 = a2*v.w + a0*R     (+ same with c* on jb)
#define OUT_ROW(rowidx, ja, aw, jb, cw)                                        \
    {                                                                          \
        float o[8];                                                            \
        o[0] = aw.w * L[ja]   + aw.y * v[ja].x + cw.w * L[jb]   + cw.y * v[jb].x + b0; \
        o[1] = aw.z * v[ja].x + aw.x * v[ja].y + cw.z * v[jb].x + cw.x * v[jb].y + b0; \
        o[2] = aw.w * v[ja].x + aw.y * v[ja].y + cw.w * v[jb].x + cw.y * v[jb].y + b0; \
        o[3] = aw.z * v[ja].y + aw.x * v[ja].z + cw.z * v[jb].y + cw.x * v[jb].z + b0; \
        o[4] = aw.w * v[ja].y + aw.y * v[ja].z + cw.w * v[jb].y + cw.y * v[jb].z + b0; \
        o[5] = aw.z * v[ja].z + aw.x * v[ja].w + cw.z * v[jb].z + cw.x * v[jb].w + b0; \
        o[6] = aw.w * v[ja].z + aw.y * v[ja].w + cw.w * v[jb].z + cw.y * v[jb].w + b0; \
        o[7] = aw.z * v[ja].w + aw.x * R[ja]   + cw.z * v[jb].w + cw.x * R[jb]   + b0; \
        stg256_cs(ob + (unsigned)(rowidx) * OW, o);                            \
    }

    OUT_ROW(0, 0, wr3, 1, wr1);
    OUT_ROW(1, 1, wr2, 2, wr0);
    OUT_ROW(2, 1, wr3, 2, wr1);
    OUT_ROW(3, 2, wr2, 3, wr0);
#undef OUT_ROW
}

extern "C" void kernel_launch(void* const* d_in, const int* in_sizes, int n_in,
                              void* d_out, int out_size) {
    const float* x = (const float*)d_in[0];
    const float* w = (const float*)d_in[1];
    const float* b = (const float*)d_in[2];
    float* out = (float*)d_out;

    const int B = in_sizes[0] / (NSLICE * H * W);   // = 8
    dim3 grid(OH / 8, B * NSLICE);                   // 64 x 192
    convT_kernel<<<grid, 128>>>(x, w, b, out);
}